// round 2
// baseline (speedup 1.0000x reference)
#include <cuda_runtime.h>
#include <math.h>

// Problem constants
#define BB 4
#define TT 2048
#define DD 2048
#define HH 16
#define HDIM 128

// Scratch (allocation-free rule: __device__ globals)
__device__ float g_qkv[(size_t)BB * TT * 3 * DD];   // (B*T, 3D) row-major
__device__ float g_y[(size_t)BB * TT * DD];         // (B*T, D) attention output

// ---------------------------------------------------------------------------
// GEMM: C[M,N] = A[M,K] @ B[N,K]^T   (both A and B row-major, K contiguous)
// 128x128 tile, BK=8, 256 threads, 8x8 per thread (2x2 blocks of 4x4).
// ---------------------------------------------------------------------------
__global__ __launch_bounds__(256)
void gemm_nt(const float* __restrict__ A, const float* __restrict__ B,
             float* __restrict__ C, int M, int N, int K) {
    __shared__ float As[8][128];
    __shared__ float Bs[8][128];
    const int tid = threadIdx.x;
    const int tx = tid & 15;
    const int ty = tid >> 4;
    const int row0 = blockIdx.y * 128;
    const int col0 = blockIdx.x * 128;
    const int lr = tid >> 1;          // 0..127: tile row loaded by this thread
    const int lk = (tid & 1) << 2;    // 0 or 4: k sub-offset

    const float* Ag = A + (size_t)(row0 + lr) * K + lk;
    const float* Bg = B + (size_t)(col0 + lr) * K + lk;

    float acc[8][8];
#pragma unroll
    for (int i = 0; i < 8; i++)
#pragma unroll
        for (int j = 0; j < 8; j++) acc[i][j] = 0.f;

    float4 av = *(const float4*)Ag;
    float4 bv = *(const float4*)Bg;

    for (int k0 = 0; k0 < K; k0 += 8) {
        As[lk + 0][lr] = av.x; As[lk + 1][lr] = av.y;
        As[lk + 2][lr] = av.z; As[lk + 3][lr] = av.w;
        Bs[lk + 0][lr] = bv.x; Bs[lk + 1][lr] = bv.y;
        Bs[lk + 2][lr] = bv.z; Bs[lk + 3][lr] = bv.w;
        __syncthreads();
        if (k0 + 8 < K) {   // prefetch next k-slab while computing
            av = *(const float4*)(Ag + k0 + 8);
            bv = *(const float4*)(Bg + k0 + 8);
        }
#pragma unroll
        for (int kk = 0; kk < 8; kk++) {
            float a[8], b[8];
            *(float4*)&a[0] = *(const float4*)&As[kk][ty * 4];
            *(float4*)&a[4] = *(const float4*)&As[kk][64 + ty * 4];
            *(float4*)&b[0] = *(const float4*)&Bs[kk][tx * 4];
            *(float4*)&b[4] = *(const float4*)&Bs[kk][64 + tx * 4];
#pragma unroll
            for (int i = 0; i < 8; i++)
#pragma unroll
                for (int j = 0; j < 8; j++)
                    acc[i][j] += a[i] * b[j];
        }
        __syncthreads();
    }

#pragma unroll
    for (int i = 0; i < 8; i++) {
        int r = row0 + ((i < 4) ? (ty * 4 + i) : (64 + ty * 4 + i - 4));
        float* Cp = C + (size_t)r * N + col0;
        *(float4*)(Cp + tx * 4) =
            make_float4(acc[i][0], acc[i][1], acc[i][2], acc[i][3]);
        *(float4*)(Cp + 64 + tx * 4) =
            make_float4(acc[i][4], acc[i][5], acc[i][6], acc[i][7]);
    }
}

// ---------------------------------------------------------------------------
// Flash attention, fp32. One CTA = one (b,h) x 64 query rows.
// 64x64 score tiles; K stored transposed + XOR-swizzled (conflict-free float4
// reads); online softmax with one quad (4 lanes) per row.
// ---------------------------------------------------------------------------
#define ATTN_SMEM_FLOATS (64 * 128 * 3 + 64 * 65 + 3 * 64)
#define ATTN_SMEM_BYTES (ATTN_SMEM_FLOATS * 4)

__global__ __launch_bounds__(256)
void attn_kernel(const float* __restrict__ qkv, const int* __restrict__ mask,
                 float* __restrict__ y) {
    extern __shared__ float sm[];
    float* Qs  = sm;               // [64][128]
    float* KsT = Qs + 64 * 128;    // [128][64] transposed + swizzled
    float* Vs  = KsT + 128 * 64;   // [64][128]
    float* Ss  = Vs + 64 * 128;    // [64][65] scores/probs (padded)
    float* m_s = Ss + 64 * 65;     // running max per row
    float* l_s = m_s + 64;         // running sum per row
    float* f_s = l_s + 64;         // rescale factor per row

    const int tid = threadIdx.x;
    const int qt = blockIdx.x;          // q tile 0..31
    const int bh = blockIdx.y;          // 0..63
    const int b = bh >> 4, h = bh & 15;

    const float* Qg = qkv + (size_t)(b * TT + qt * 64) * (3 * DD) + h * HDIM;
    const float* Kg = qkv + (size_t)(b * TT) * (3 * DD) + h * HDIM + DD;
    const int* mg = mask + b * TT;

    const int g = tid & 31;   // float4 group along headdim
    const int tl = tid >> 5;  // token sub-row

    // Load Q tile (64 x 128)
#pragma unroll
    for (int it = 0; it < 8; it++) {
        int t = tl + it * 8;
        *(float4*)(Qs + t * 128 + g * 4) =
            *(const float4*)(Qg + (size_t)t * (3 * DD) + g * 4);
    }
    if (tid < 64) { m_s[tid] = -1e30f; l_s[tid] = 0.f; }

    float o[32];
#pragma unroll
    for (int i = 0; i < 32; i++) o[i] = 0.f;

    const int warp = tid >> 5, lane = tid & 31;
    const int prow = ((warp & 1) << 5) | lane;  // PV row: 0..63
    const int pcol = (warp >> 1) << 5;          // PV col group base (0/32/64/96)
    const int sty = tid >> 4, stx = tid & 15;   // score-stage 16x16 map
    const float scale = 0.08838834764831845f;   // 1/sqrt(128)

#pragma unroll 1
    for (int kt = 0; kt < TT / 64; kt++) {
        __syncthreads();  // protect smem from previous iteration's readers

        // Load K tile transposed (+swizzle) and V tile straight
#pragma unroll
        for (int it = 0; it < 8; it++) {
            int t = tl + it * 8;
            const float* kp = Kg + (size_t)(kt * 64 + t) * (3 * DD) + g * 4;
            float4 k4 = *(const float4*)kp;
            float4 v4 = *(const float4*)(kp + DD);  // V is D floats after K
            float kvals[4] = {k4.x, k4.y, k4.z, k4.w};
#pragma unroll
            for (int u = 0; u < 4; u++) {
                int kk = g * 4 + u;
                int f = (t >> 2) ^ (kk & 15);
                KsT[kk * 64 + f * 4 + (t & 3)] = kvals[u];
            }
            *(float4*)(Vs + t * 128 + g * 4) = v4;
        }
        __syncthreads();

        // Scores: S[64][64] = Q_tile @ K_tile^T, each thread 4x4
        {
            float ss[4][4];
#pragma unroll
            for (int i = 0; i < 4; i++)
#pragma unroll
                for (int j = 0; j < 4; j++) ss[i][j] = 0.f;

#pragma unroll 8
            for (int k4 = 0; k4 < 32; k4++) {
                float qb[4][4];
#pragma unroll
                for (int i = 0; i < 4; i++) {
                    float4 qv = *(const float4*)(Qs + (sty * 4 + i) * 128 + k4 * 4);
                    qb[i][0] = qv.x; qb[i][1] = qv.y;
                    qb[i][2] = qv.z; qb[i][3] = qv.w;
                }
#pragma unroll
                for (int kkk = 0; kkk < 4; kkk++) {
                    int kk = k4 * 4 + kkk;
                    int f = stx ^ (kk & 15);
                    float4 kv = *(const float4*)(KsT + kk * 64 + f * 4);
                    float kb[4] = {kv.x, kv.y, kv.z, kv.w};
#pragma unroll
                    for (int i = 0; i < 4; i++)
#pragma unroll
                        for (int j = 0; j < 4; j++)
                            ss[i][j] += qb[i][kkk] * kb[j];
                }
            }
            int mk[4];
#pragma unroll
            for (int j = 0; j < 4; j++) mk[j] = mg[kt * 64 + stx * 4 + j];
#pragma unroll
            for (int i = 0; i < 4; i++)
#pragma unroll
                for (int j = 0; j < 4; j++) {
                    float v = ss[i][j] * scale;
                    if (mk[j] == 0) v = -1e30f;
                    Ss[(sty * 4 + i) * 65 + stx * 4 + j] = v;
                }
        }
        __syncthreads();

        // Online softmax: 4 lanes (a quad) per row
        {
            int r = tid >> 2, qq = tid & 3;
            float* srow = Ss + r * 65 + qq * 16;
            float mx = -1e30f;
#pragma unroll
            for (int j = 0; j < 16; j++) mx = fmaxf(mx, srow[j]);
            mx = fmaxf(mx, __shfl_xor_sync(0xffffffffu, mx, 1));
            mx = fmaxf(mx, __shfl_xor_sync(0xffffffffu, mx, 2));
            float mold = m_s[r];
            float mnew = fmaxf(mold, mx);
            float sum = 0.f;
#pragma unroll
            for (int j = 0; j < 16; j++) {
                float p = __expf(srow[j] - mnew);
                srow[j] = p;
                sum += p;
            }
            sum += __shfl_xor_sync(0xffffffffu, sum, 1);
            sum += __shfl_xor_sync(0xffffffffu, sum, 2);
            if (qq == 0) {
                float fac = __expf(mold - mnew);
                f_s[r] = fac;
                m_s[r] = mnew;
                l_s[r] = l_s[r] * fac + sum;
            }
        }
        __syncthreads();

        // Rescale accumulators and accumulate P @ V
        {
            float fac = f_s[prow];
#pragma unroll
            for (int i = 0; i < 32; i++) o[i] *= fac;
            const float* srow = Ss + prow * 65;
#pragma unroll 4
            for (int kk = 0; kk < 64; kk++) {
                float p = srow[kk];
                const float* vr = Vs + kk * 128 + pcol;  // broadcast across warp
#pragma unroll
                for (int c4 = 0; c4 < 8; c4++) {
                    float4 vv = *(const float4*)(vr + c4 * 4);
                    o[c4 * 4 + 0] += p * vv.x;
                    o[c4 * 4 + 1] += p * vv.y;
                    o[c4 * 4 + 2] += p * vv.z;
                    o[c4 * 4 + 3] += p * vv.w;
                }
            }
        }
    }

    // Normalize and write y in (B,T,D) layout with D = h*128 + col
    float inv = 1.f / l_s[prow];
    float* yp = y + (size_t)(b * TT + qt * 64 + prow) * DD + h * HDIM + pcol;
#pragma unroll
    for (int c4 = 0; c4 < 8; c4++) {
        *(float4*)(yp + c4 * 4) = make_float4(o[c4 * 4 + 0] * inv, o[c4 * 4 + 1] * inv,
                                              o[c4 * 4 + 2] * inv, o[c4 * 4 + 3] * inv);
    }
}

// ---------------------------------------------------------------------------
// Launch
// ---------------------------------------------------------------------------
extern "C" void kernel_launch(void* const* d_in, const int* in_sizes, int n_in,
                              void* d_out, int out_size) {
    const float* x     = (const float*)d_in[0];
    const int*   mask  = (const int*)d_in[1];
    const float* w_qkv = (const float*)d_in[2];
    const float* w_o   = (const float*)d_in[3];
    float* out = (float*)d_out;

    float *qkv, *yb;
    cudaGetSymbolAddress((void**)&qkv, g_qkv);
    cudaGetSymbolAddress((void**)&yb, g_y);
    cudaFuncSetAttribute(attn_kernel, cudaFuncAttributeMaxDynamicSharedMemorySize,
                         ATTN_SMEM_BYTES);

    // QKV = X @ Wqkv^T : (8192 x 2048) x (6144 x 2048)^T
    gemm_nt<<<dim3(3 * DD / 128, BB * TT / 128), 256>>>(x, w_qkv, qkv,
                                                        BB * TT, 3 * DD, DD);
    // Attention -> y (B,T,D)
    attn_kernel<<<dim3(TT / 64, BB * HH), 256, ATTN_SMEM_BYTES>>>(qkv, mask, yb);
    // out = Y @ Wo^T : (8192 x 2048) x (2048 x 2048)^T
    gemm_nt<<<dim3(DD / 128, BB * TT / 128), 256>>>(yb, w_o, out,
                                                    BB * TT, DD, DD);
}

// round 4
// speedup vs baseline: 1.3734x; 1.3734x over previous
#include <cuda_runtime.h>
#include <cstdint>
#include <math.h>

using u32 = unsigned int;

// Problem constants
#define BB 4
#define TT 2048
#define DD 2048
#define HH 16
#define HDIM 128

// Scratch (allocation-free rule: __device__ globals)
__device__ float g_qkv[(size_t)BB * TT * 3 * DD];   // (B*T, 3D) row-major
__device__ float g_y[(size_t)BB * TT * DD];         // (B*T, D) attention output

// ---------------------------------------------------------------------------
// TF32 tensor-core GEMM: C[M,N] = A[M,K] @ B[N,K]^T  (both row-major, K contig)
// 128x128x32 tile, 256 threads (8 warps, 4x2), warp tile 32x64,
// mma.sync.aligned.m16n8k8.row.col.f32.tf32.tf32.f32
// ---------------------------------------------------------------------------
#define BM 128
#define BN 128
#define BKK 32
#define LDS_STRIDE (BKK + 4)   // 36: conflict-free fragment loads

__device__ __forceinline__ u32 f2tf32(float f) {
    u32 u;
    asm("cvt.rna.tf32.f32 %0, %1;" : "=r"(u) : "f"(f));
    return u;
}

__device__ __forceinline__ void mma_tf32(float* d, const u32* a, const u32* b) {
    asm volatile(
        "mma.sync.aligned.m16n8k8.row.col.f32.tf32.tf32.f32 "
        "{%0,%1,%2,%3}, {%4,%5,%6,%7}, {%8,%9}, {%0,%1,%2,%3};"
        : "+f"(d[0]), "+f"(d[1]), "+f"(d[2]), "+f"(d[3])
        : "r"(a[0]), "r"(a[1]), "r"(a[2]), "r"(a[3]), "r"(b[0]), "r"(b[1]));
}

__global__ __launch_bounds__(256)
void gemm_nt_tf32(const float* __restrict__ A, const float* __restrict__ B,
                  float* __restrict__ C, int M, int N, int K) {
    __shared__ u32 As[BM][LDS_STRIDE];
    __shared__ u32 Bs[BN][LDS_STRIDE];

    const int tid = threadIdx.x;
    const int warp = tid >> 5, lane = tid & 31;
    const int wm = warp >> 1;          // 0..3 -> m offset wm*32
    const int wn = warp & 1;           // 0..1 -> n offset wn*64
    const int row0 = blockIdx.y * BM;
    const int col0 = blockIdx.x * BN;
    const int lr = tid >> 1;           // tile row loaded by this thread
    const int half = tid & 1;          // which 16-float half of the k-slab

    const float* Ag = A + (size_t)(row0 + lr) * K + half * 16;
    const float* Bg = B + (size_t)(col0 + lr) * K + half * 16;

    float acc[2][8][4];
#pragma unroll
    for (int f = 0; f < 2; f++)
#pragma unroll
        for (int g = 0; g < 8; g++)
#pragma unroll
            for (int i = 0; i < 4; i++) acc[f][g][i] = 0.f;

    float4 apre[4], bpre[4];
#pragma unroll
    for (int i = 0; i < 4; i++) {
        apre[i] = *(const float4*)(Ag + i * 4);
        bpre[i] = *(const float4*)(Bg + i * 4);
    }

    const int fr = lane >> 2;   // fragment row (groupID)
    const int fc = lane & 3;    // fragment col (threadID in group)

    for (int k0 = 0; k0 < K; k0 += BKK) {
        // Store prefetched slab to smem, converting fp32 -> tf32 bits
#pragma unroll
        for (int i = 0; i < 4; i++) {
            uint4 ua = make_uint4(f2tf32(apre[i].x), f2tf32(apre[i].y),
                                  f2tf32(apre[i].z), f2tf32(apre[i].w));
            uint4 ub = make_uint4(f2tf32(bpre[i].x), f2tf32(bpre[i].y),
                                  f2tf32(bpre[i].z), f2tf32(bpre[i].w));
            *(uint4*)&As[lr][half * 16 + i * 4] = ua;
            *(uint4*)&Bs[lr][half * 16 + i * 4] = ub;
        }
        __syncthreads();

        if (k0 + BKK < K) {
#pragma unroll
            for (int i = 0; i < 4; i++) {
                apre[i] = *(const float4*)(Ag + k0 + BKK + i * 4);
                bpre[i] = *(const float4*)(Bg + k0 + BKK + i * 4);
            }
        }

#pragma unroll
        for (int ks = 0; ks < BKK; ks += 8) {
            u32 a[2][4], b[8][2];
#pragma unroll
            for (int f = 0; f < 2; f++) {
                int mr = wm * 32 + f * 16 + fr;
                a[f][0] = As[mr][ks + fc];
                a[f][1] = As[mr + 8][ks + fc];
                a[f][2] = As[mr][ks + fc + 4];
                a[f][3] = As[mr + 8][ks + fc + 4];
            }
#pragma unroll
            for (int g = 0; g < 8; g++) {
                int nr = wn * 64 + g * 8 + fr;
                b[g][0] = Bs[nr][ks + fc];
                b[g][1] = Bs[nr][ks + fc + 4];
            }
#pragma unroll
            for (int f = 0; f < 2; f++)
#pragma unroll
                for (int g = 0; g < 8; g++)
                    mma_tf32(acc[f][g], a[f], b[g]);
        }
        __syncthreads();
    }

    // Epilogue: c0/c1 at (row=fr, col=2*fc,2*fc+1); c2/c3 at row=fr+8
#pragma unroll
    for (int f = 0; f < 2; f++) {
#pragma unroll
        for (int g = 0; g < 8; g++) {
            int rr = row0 + wm * 32 + f * 16 + fr;
            int cc = col0 + wn * 64 + g * 8 + 2 * fc;
            *(float2*)(C + (size_t)rr * N + cc) =
                make_float2(acc[f][g][0], acc[f][g][1]);
            *(float2*)(C + (size_t)(rr + 8) * N + cc) =
                make_float2(acc[f][g][2], acc[f][g][3]);
        }
    }
}

// ---------------------------------------------------------------------------
// Flash attention, fp32. One CTA = one (b,h) x 64 query rows.
// ---------------------------------------------------------------------------
#define ATTN_SMEM_FLOATS (64 * 128 * 3 + 64 * 65 + 3 * 64)
#define ATTN_SMEM_BYTES (ATTN_SMEM_FLOATS * 4)

__global__ __launch_bounds__(256)
void attn_kernel(const float* __restrict__ qkv, const int* __restrict__ mask,
                 float* __restrict__ y) {
    extern __shared__ float sm[];
    float* Qs  = sm;               // [64][128]
    float* KsT = Qs + 64 * 128;    // [128][64] transposed + swizzled
    float* Vs  = KsT + 128 * 64;   // [64][128]
    float* Ss  = Vs + 64 * 128;    // [64][65]
    float* m_s = Ss + 64 * 65;
    float* l_s = m_s + 64;
    float* f_s = l_s + 64;

    const int tid = threadIdx.x;
    const int qt = blockIdx.x;
    const int bh = blockIdx.y;
    const int b = bh >> 4, h = bh & 15;

    const float* Qg = qkv + (size_t)(b * TT + qt * 64) * (3 * DD) + h * HDIM;
    const float* Kg = qkv + (size_t)(b * TT) * (3 * DD) + h * HDIM + DD;
    const int* mg = mask + b * TT;

    const int g = tid & 31;
    const int tl = tid >> 5;

#pragma unroll
    for (int it = 0; it < 8; it++) {
        int t = tl + it * 8;
        *(float4*)(Qs + t * 128 + g * 4) =
            *(const float4*)(Qg + (size_t)t * (3 * DD) + g * 4);
    }
    if (tid < 64) { m_s[tid] = -1e30f; l_s[tid] = 0.f; }

    float o[32];
#pragma unroll
    for (int i = 0; i < 32; i++) o[i] = 0.f;

    const int warp = tid >> 5, lane = tid & 31;
    const int prow = ((warp & 1) << 5) | lane;
    const int pcol = (warp >> 1) << 5;
    const int sty = tid >> 4, stx = tid & 15;
    const float scale = 0.08838834764831845f;

#pragma unroll 1
    for (int kt = 0; kt < TT / 64; kt++) {
        __syncthreads();

#pragma unroll
        for (int it = 0; it < 8; it++) {
            int t = tl + it * 8;
            const float* kp = Kg + (size_t)(kt * 64 + t) * (3 * DD) + g * 4;
            float4 k4 = *(const float4*)kp;
            float4 v4 = *(const float4*)(kp + DD);
            float kvals[4] = {k4.x, k4.y, k4.z, k4.w};
#pragma unroll
            for (int u = 0; u < 4; u++) {
                int kk = g * 4 + u;
                int f = (t >> 2) ^ (kk & 15);
                KsT[kk * 64 + f * 4 + (t & 3)] = kvals[u];
            }
            *(float4*)(Vs + t * 128 + g * 4) = v4;
        }
        __syncthreads();

        {
            float ss[4][4];
#pragma unroll
            for (int i = 0; i < 4; i++)
#pragma unroll
                for (int j = 0; j < 4; j++) ss[i][j] = 0.f;

#pragma unroll 8
            for (int k4 = 0; k4 < 32; k4++) {
                float qb[4][4];
#pragma unroll
                for (int i = 0; i < 4; i++) {
                    float4 qv = *(const float4*)(Qs + (sty * 4 + i) * 128 + k4 * 4);
                    qb[i][0] = qv.x; qb[i][1] = qv.y;
                    qb[i][2] = qv.z; qb[i][3] = qv.w;
                }
#pragma unroll
                for (int kkk = 0; kkk < 4; kkk++) {
                    int kk = k4 * 4 + kkk;
                    int f = stx ^ (kk & 15);
                    float4 kv = *(const float4*)(KsT + kk * 64 + f * 4);
                    float kb[4] = {kv.x, kv.y, kv.z, kv.w};
#pragma unroll
                    for (int i = 0; i < 4; i++)
#pragma unroll
                        for (int j = 0; j < 4; j++)
                            ss[i][j] += qb[i][kkk] * kb[j];
                }
            }
            int mk[4];
#pragma unroll
            for (int j = 0; j < 4; j++) mk[j] = mg[kt * 64 + stx * 4 + j];
#pragma unroll
            for (int i = 0; i < 4; i++)
#pragma unroll
                for (int j = 0; j < 4; j++) {
                    float v = ss[i][j] * scale;
                    if (mk[j] == 0) v = -1e30f;
                    Ss[(sty * 4 + i) * 65 + stx * 4 + j] = v;
                }
        }
        __syncthreads();

        {
            int r = tid >> 2, qq = tid & 3;
            float* srow = Ss + r * 65 + qq * 16;
            float mx = -1e30f;
#pragma unroll
            for (int j = 0; j < 16; j++) mx = fmaxf(mx, srow[j]);
            mx = fmaxf(mx, __shfl_xor_sync(0xffffffffu, mx, 1));
            mx = fmaxf(mx, __shfl_xor_sync(0xffffffffu, mx, 2));
            float mold = m_s[r];
            float mnew = fmaxf(mold, mx);
            float sum = 0.f;
#pragma unroll
            for (int j = 0; j < 16; j++) {
                float p = __expf(srow[j] - mnew);
                srow[j] = p;
                sum += p;
            }
            sum += __shfl_xor_sync(0xffffffffu, sum, 1);
            sum += __shfl_xor_sync(0xffffffffu, sum, 2);
            if (qq == 0) {
                float fac = __expf(mold - mnew);
                f_s[r] = fac;
                m_s[r] = mnew;
                l_s[r] = l_s[r] * fac + sum;
            }
        }
        __syncthreads();

        {
            float fac = f_s[prow];
#pragma unroll
            for (int i = 0; i < 32; i++) o[i] *= fac;
            const float* srow = Ss + prow * 65;
#pragma unroll 4
            for (int kk = 0; kk < 64; kk++) {
                float p = srow[kk];
                const float* vr = Vs + kk * 128 + pcol;
#pragma unroll
                for (int c4 = 0; c4 < 8; c4++) {
                    float4 vv = *(const float4*)(vr + c4 * 4);
                    o[c4 * 4 + 0] += p * vv.x;
                    o[c4 * 4 + 1] += p * vv.y;
                    o[c4 * 4 + 2] += p * vv.z;
                    o[c4 * 4 + 3] += p * vv.w;
                }
            }
        }
    }

    float inv = 1.f / l_s[prow];
    float* yp = y + (size_t)(b * TT + qt * 64 + prow) * DD + h * HDIM + pcol;
#pragma unroll
    for (int c4 = 0; c4 < 8; c4++) {
        *(float4*)(yp + c4 * 4) = make_float4(o[c4 * 4 + 0] * inv, o[c4 * 4 + 1] * inv,
                                              o[c4 * 4 + 2] * inv, o[c4 * 4 + 3] * inv);
    }
}

// ---------------------------------------------------------------------------
// Launch
// ---------------------------------------------------------------------------
extern "C" void kernel_launch(void* const* d_in, const int* in_sizes, int n_in,
                              void* d_out, int out_size) {
    const float* x     = (const float*)d_in[0];
    const int*   mask  = (const int*)d_in[1];
    const float* w_qkv = (const float*)d_in[2];
    const float* w_o   = (const float*)d_in[3];
    float* out = (float*)d_out;

    float *qkv, *yb;
    cudaGetSymbolAddress((void**)&qkv, g_qkv);
    cudaGetSymbolAddress((void**)&yb, g_y);
    cudaFuncSetAttribute(attn_kernel, cudaFuncAttributeMaxDynamicSharedMemorySize,
                         ATTN_SMEM_BYTES);

    // QKV = X @ Wqkv^T : (8192 x 2048) x (6144 x 2048)^T
    gemm_nt_tf32<<<dim3(3 * DD / BN, BB * TT / BM), 256>>>(x, w_qkv, qkv,
                                                           BB * TT, 3 * DD, DD);
    // Attention -> y (B,T,D)
    attn_kernel<<<dim3(TT / 64, BB * HH), 256, ATTN_SMEM_BYTES>>>(qkv, mask, yb);
    // out = Y @ Wo^T : (8192 x 2048) x (2048 x 2048)^T
    gemm_nt_tf32<<<dim3(DD / BN, BB * TT / BM), 256>>>(yb, w_o, out,
                                                       BB * TT, DD, DD);
}

// round 7
// speedup vs baseline: 2.6283x; 1.9137x over previous
#include <cuda_runtime.h>
#include <cuda_bf16.h>
#include <cstdint>
#include <math.h>

using u32 = unsigned int;

// Problem constants
#define BB 4
#define TT 2048
#define DD 2048
#define HH 16
#define HDIM 128

// Scratch (allocation-free rule: __device__ globals)
__device__ float g_qkv[(size_t)BB * TT * 3 * DD];   // (B*T, 3D) row-major
__device__ float g_y[(size_t)BB * TT * DD];         // (B*T, D) attention output

// ---------------------------------------------------------------------------
// TF32 tensor-core GEMM (unchanged from R4, known-pass)
// ---------------------------------------------------------------------------
#define BM 128
#define BN 128
#define BKK 32
#define LDS_STRIDE (BKK + 4)

__device__ __forceinline__ u32 f2tf32(float f) {
    u32 u;
    asm("cvt.rna.tf32.f32 %0, %1;" : "=r"(u) : "f"(f));
    return u;
}

__device__ __forceinline__ void mma_tf32(float* d, const u32* a, const u32* b) {
    asm volatile(
        "mma.sync.aligned.m16n8k8.row.col.f32.tf32.tf32.f32 "
        "{%0,%1,%2,%3}, {%4,%5,%6,%7}, {%8,%9}, {%0,%1,%2,%3};"
        : "+f"(d[0]), "+f"(d[1]), "+f"(d[2]), "+f"(d[3])
        : "r"(a[0]), "r"(a[1]), "r"(a[2]), "r"(a[3]), "r"(b[0]), "r"(b[1]));
}

__global__ __launch_bounds__(256)
void gemm_nt_tf32(const float* __restrict__ A, const float* __restrict__ B,
                  float* __restrict__ C, int M, int N, int K) {
    __shared__ u32 As[BM][LDS_STRIDE];
    __shared__ u32 Bs[BN][LDS_STRIDE];

    const int tid = threadIdx.x;
    const int warp = tid >> 5, lane = tid & 31;
    const int wm = warp >> 1;
    const int wn = warp & 1;
    const int row0 = blockIdx.y * BM;
    const int col0 = blockIdx.x * BN;
    const int lr = tid >> 1;
    const int half = tid & 1;

    const float* Ag = A + (size_t)(row0 + lr) * K + half * 16;
    const float* Bg = B + (size_t)(col0 + lr) * K + half * 16;

    float acc[2][8][4];
#pragma unroll
    for (int f = 0; f < 2; f++)
#pragma unroll
        for (int g = 0; g < 8; g++)
#pragma unroll
            for (int i = 0; i < 4; i++) acc[f][g][i] = 0.f;

    float4 apre[4], bpre[4];
#pragma unroll
    for (int i = 0; i < 4; i++) {
        apre[i] = *(const float4*)(Ag + i * 4);
        bpre[i] = *(const float4*)(Bg + i * 4);
    }

    const int fr = lane >> 2;
    const int fc = lane & 3;

    for (int k0 = 0; k0 < K; k0 += BKK) {
#pragma unroll
        for (int i = 0; i < 4; i++) {
            uint4 ua = make_uint4(f2tf32(apre[i].x), f2tf32(apre[i].y),
                                  f2tf32(apre[i].z), f2tf32(apre[i].w));
            uint4 ub = make_uint4(f2tf32(bpre[i].x), f2tf32(bpre[i].y),
                                  f2tf32(bpre[i].z), f2tf32(bpre[i].w));
            *(uint4*)&As[lr][half * 16 + i * 4] = ua;
            *(uint4*)&Bs[lr][half * 16 + i * 4] = ub;
        }
        __syncthreads();

        if (k0 + BKK < K) {
#pragma unroll
            for (int i = 0; i < 4; i++) {
                apre[i] = *(const float4*)(Ag + k0 + BKK + i * 4);
                bpre[i] = *(const float4*)(Bg + k0 + BKK + i * 4);
            }
        }

#pragma unroll
        for (int ks = 0; ks < BKK; ks += 8) {
            u32 a[2][4], b[8][2];
#pragma unroll
            for (int f = 0; f < 2; f++) {
                int mr = wm * 32 + f * 16 + fr;
                a[f][0] = As[mr][ks + fc];
                a[f][1] = As[mr + 8][ks + fc];
                a[f][2] = As[mr][ks + fc + 4];
                a[f][3] = As[mr + 8][ks + fc + 4];
            }
#pragma unroll
            for (int g = 0; g < 8; g++) {
                int nr = wn * 64 + g * 8 + fr;
                b[g][0] = Bs[nr][ks + fc];
                b[g][1] = Bs[nr][ks + fc + 4];
            }
#pragma unroll
            for (int f = 0; f < 2; f++)
#pragma unroll
                for (int g = 0; g < 8; g++)
                    mma_tf32(acc[f][g], a[f], b[g]);
        }
        __syncthreads();
    }

#pragma unroll
    for (int f = 0; f < 2; f++) {
#pragma unroll
        for (int g = 0; g < 8; g++) {
            int rr = row0 + wm * 32 + f * 16 + fr;
            int cc = col0 + wn * 64 + g * 8 + 2 * fc;
            *(float2*)(C + (size_t)rr * N + cc) =
                make_float2(acc[f][g][0], acc[f][g][1]);
            *(float2*)(C + (size_t)(rr + 8) * N + cc) =
                make_float2(acc[f][g][2], acc[f][g][3]);
        }
    }
}

// ===========================================================================
// Flash attention v3: HMMA bf16 with two-term splits on BOTH matmuls.
// QK^T: QhKh + QlKh + QhKl.  PV: PhVh + PhVl + PlVh.  exp: FFMA poly.
// 128 threads (4 warps x 16 q-rows = 64 rows / CTA), kv chunks of 64.
// ===========================================================================
#define KH_OFF 0
#define KL_OFF 16384
#define VH_OFF 32768
#define VL_OFF 49152
#define BIAS_OFF 65536
#define ATTN2_SMEM (65536 + 256)

__device__ __forceinline__ u32 smem_u32(const void* p) {
    u32 a;
    asm("{ .reg .u64 t; cvta.to.shared.u64 t, %1; cvt.u32.u64 %0, t; }"
        : "=r"(a) : "l"(p));
    return a;
}

__device__ __forceinline__ u32 packbf(float lo, float hi) {
    u32 r;
    asm("cvt.rn.bf16x2.f32 %0, %1, %2;" : "=r"(r) : "f"(hi), "f"(lo));
    return r;
}

__device__ __forceinline__ void mma16816(float* c, const u32* a, const u32* b) {
    asm volatile(
        "mma.sync.aligned.m16n8k16.row.col.f32.bf16.bf16.f32 "
        "{%0,%1,%2,%3}, {%4,%5,%6,%7}, {%8,%9}, {%0,%1,%2,%3};"
        : "+f"(c[0]), "+f"(c[1]), "+f"(c[2]), "+f"(c[3])
        : "r"(a[0]), "r"(a[1]), "r"(a[2]), "r"(a[3]), "r"(b[0]), "r"(b[1]));
}

__device__ __forceinline__ void ldsm_x2(u32& r0, u32& r1, u32 addr) {
    asm volatile("ldmatrix.sync.aligned.m8n8.x2.shared.b16 {%0,%1}, [%2];"
                 : "=r"(r0), "=r"(r1) : "r"(addr));
}

__device__ __forceinline__ void ldsm_x2_t(u32& r0, u32& r1, u32 addr) {
    asm volatile("ldmatrix.sync.aligned.m8n8.x2.trans.shared.b16 {%0,%1}, [%2];"
                 : "=r"(r0), "=r"(r1) : "r"(addr));
}

// exp2 for t <= 0, FFMA-only (no MUFU). |err| ~1e-7 rel.
__device__ __forceinline__ float exp2_fast(float t) {
    t = fmaxf(t, -126.f);
    float k = rintf(t);
    float f = t - k;
    float u = f * 0.69314718056f;
    float p = 0.0013888889f;
    p = fmaf(p, u, 0.008333334f);
    p = fmaf(p, u, 0.041666668f);
    p = fmaf(p, u, 0.16666667f);
    p = fmaf(p, u, 0.5f);
    p = fmaf(p, u, 1.0f);
    p = fmaf(p, u, 1.0f);
    return __int_as_float(((int)k + 127) << 23) * p;
}

// split fp32 -> (hi bf16 as float, lo = residual)
__device__ __forceinline__ void bsplit(float v, float& hi, float& lo) {
    __nv_bfloat16 h = __float2bfloat16_rn(v);
    hi = __bfloat162float(h);
    lo = v - hi;
}

// pack two floats into hi-pair and lo-pair bf16x2
__device__ __forceinline__ void pack_split2(float a, float b, u32& hp, u32& lp) {
    float ha, la, hb, lb;
    bsplit(a, ha, la);
    bsplit(b, hb, lb);
    hp = packbf(ha, hb);
    lp = packbf(la, lb);
}

// 8 floats -> 16B bf16 hi chunk + lo chunk
__device__ __forceinline__ void split8_u4(const float* v, uint4& hc, uint4& lc) {
    float h[8], l[8];
#pragma unroll
    for (int i = 0; i < 8; i++) bsplit(v[i], h[i], l[i]);
    hc = make_uint4(packbf(h[0], h[1]), packbf(h[2], h[3]),
                    packbf(h[4], h[5]), packbf(h[6], h[7]));
    lc = make_uint4(packbf(l[0], l[1]), packbf(l[2], l[3]),
                    packbf(l[4], l[5]), packbf(l[6], l[7]));
}

__global__ __launch_bounds__(128)
void attn_mma(const float* __restrict__ qkv, const int* __restrict__ mask,
              float* __restrict__ y) {
    extern __shared__ char smA[];
    const u32 sbase = smem_u32(smA);
    float* biasS = (float*)(smA + BIAS_OFF);

    const int tid = threadIdx.x;
    const int warp = tid >> 5, lane = tid & 31;
    const int fr = lane >> 2, fc = lane & 3;
    const int qt = blockIdx.x;          // 0..31
    const int bh = blockIdx.y;          // 0..63
    const int b = bh >> 4, h = bh & 15;

    const float C = 0.12751743f;        // (1/sqrt(128)) * log2(e)

    // ---- Load Q fragments (hi/lo) directly from global ----
    u32 Qh[8][4], Ql[8][4];
    {
        const float* Qg = qkv + (size_t)(b * TT + qt * 64 + warp * 16) * (3 * DD)
                        + h * HDIM;
#pragma unroll
        for (int kf = 0; kf < 8; kf++) {
            const float* p0 = Qg + (size_t)fr * (3 * DD) + kf * 16 + 2 * fc;
            const float* p1 = p0 + (size_t)8 * (3 * DD);
            float2 v0 = *(const float2*)p0;
            float2 v1 = *(const float2*)p1;
            float2 v2 = *(const float2*)(p0 + 8);
            float2 v3 = *(const float2*)(p1 + 8);
            pack_split2(v0.x, v0.y, Qh[kf][0], Ql[kf][0]);
            pack_split2(v1.x, v1.y, Qh[kf][1], Ql[kf][1]);
            pack_split2(v2.x, v2.y, Qh[kf][2], Ql[kf][2]);
            pack_split2(v3.x, v3.y, Qh[kf][3], Ql[kf][3]);
        }
    }

    float o[16][4];
#pragma unroll
    for (int n = 0; n < 16; n++)
#pragma unroll
        for (int j = 0; j < 4; j++) o[n][j] = 0.f;
    float m0 = -1e30f, m1 = -1e30f, l0 = 0.f, l1 = 0.f;

    const float* KgB = qkv + (size_t)(b * TT) * (3 * DD) + DD + h * HDIM;
    const int* mg = mask + b * TT;

#pragma unroll 1
    for (int kt = 0; kt < TT / 64; kt++) {
        __syncthreads();
        // ---- Convert K (hi+lo) and V (hi+lo) chunk into swizzled bf16 smem ----
#pragma unroll
        for (int i = 0; i < 8; i++) {
            int sid = tid + i * 128;            // 0..1023
            int row = sid >> 4, c = sid & 15;   // row: kv token, c: 16B chunk
            const float* kg = KgB + (size_t)(kt * 64 + row) * (3 * DD) + c * 8;
            float kv[8], vv[8];
            *(float4*)&kv[0] = *(const float4*)kg;
            *(float4*)&kv[4] = *(const float4*)(kg + 4);
            *(float4*)&vv[0] = *(const float4*)(kg + DD);
            *(float4*)&vv[4] = *(const float4*)(kg + DD + 4);
            u32 off = row * 256 + (((u32)(c ^ (row & 7))) << 4);
            uint4 hc, lc;
            split8_u4(kv, hc, lc);
            *(uint4*)(smA + KH_OFF + off) = hc;
            *(uint4*)(smA + KL_OFF + off) = lc;
            split8_u4(vv, hc, lc);
            *(uint4*)(smA + VH_OFF + off) = hc;
            *(uint4*)(smA + VL_OFF + off) = lc;
        }
        if (tid < 64)
            biasS[tid] = mg[kt * 64 + tid] ? 0.f : -1e30f;
        __syncthreads();

        // ---- S = Q K^T (bf16x3) ----
        float s[8][4];
#pragma unroll
        for (int n = 0; n < 8; n++)
#pragma unroll
            for (int j = 0; j < 4; j++) s[n][j] = 0.f;

        const int lrow8 = lane & 7;
        const int lsel = (lane >> 3) & 1;
#pragma unroll
        for (int kf = 0; kf < 8; kf++) {
#pragma unroll
            for (int n = 0; n < 8; n++) {
                int trow = n * 8 + lrow8;
                int tc = kf * 2 + lsel;
                u32 off = (u32)(trow * 256) + ((u32)(tc ^ (trow & 7)) << 4);
                u32 bhf[2], blf[2];
                ldsm_x2(bhf[0], bhf[1], sbase + KH_OFF + off);
                ldsm_x2(blf[0], blf[1], sbase + KL_OFF + off);
                mma16816(s[n], Qh[kf], bhf);
                mma16816(s[n], Ql[kf], bhf);
                mma16816(s[n], Qh[kf], blf);
            }
        }

        // ---- online softmax in log2 domain ----
        float mx0 = -1e30f, mx1 = -1e30f;
#pragma unroll
        for (int n = 0; n < 8; n++) {
            float2 bb = *(float2*)&biasS[n * 8 + 2 * fc];
            s[n][0] = fmaf(s[n][0], C, bb.x);
            s[n][1] = fmaf(s[n][1], C, bb.y);
            s[n][2] = fmaf(s[n][2], C, bb.x);
            s[n][3] = fmaf(s[n][3], C, bb.y);
            mx0 = fmaxf(mx0, fmaxf(s[n][0], s[n][1]));
            mx1 = fmaxf(mx1, fmaxf(s[n][2], s[n][3]));
        }
        mx0 = fmaxf(mx0, __shfl_xor_sync(0xffffffffu, mx0, 1));
        mx0 = fmaxf(mx0, __shfl_xor_sync(0xffffffffu, mx0, 2));
        mx1 = fmaxf(mx1, __shfl_xor_sync(0xffffffffu, mx1, 1));
        mx1 = fmaxf(mx1, __shfl_xor_sync(0xffffffffu, mx1, 2));

        float m0n = fmaxf(m0, mx0), m1n = fmaxf(m1, mx1);
        float f0 = exp2_fast(m0 - m0n), f1 = exp2_fast(m1 - m1n);
        m0 = m0n; m1 = m1n;

        float sum0 = 0.f, sum1 = 0.f;
#pragma unroll
        for (int n = 0; n < 8; n++) {
            s[n][0] = exp2_fast(s[n][0] - m0n);
            s[n][1] = exp2_fast(s[n][1] - m0n);
            s[n][2] = exp2_fast(s[n][2] - m1n);
            s[n][3] = exp2_fast(s[n][3] - m1n);
            sum0 += s[n][0] + s[n][1];
            sum1 += s[n][2] + s[n][3];
        }
        sum0 += __shfl_xor_sync(0xffffffffu, sum0, 1);
        sum0 += __shfl_xor_sync(0xffffffffu, sum0, 2);
        sum1 += __shfl_xor_sync(0xffffffffu, sum1, 1);
        sum1 += __shfl_xor_sync(0xffffffffu, sum1, 2);
        l0 = l0 * f0 + sum0;
        l1 = l1 * f1 + sum1;

        // rescale accumulators
#pragma unroll
        for (int n = 0; n < 16; n++) {
            o[n][0] *= f0; o[n][1] *= f0;
            o[n][2] *= f1; o[n][3] *= f1;
        }

        // pack P -> hi/lo A fragments (bf16 split)
        u32 pah[4][4], pal[4][4];
#pragma unroll
        for (int kf = 0; kf < 4; kf++) {
            pack_split2(s[2 * kf][0], s[2 * kf][1], pah[kf][0], pal[kf][0]);
            pack_split2(s[2 * kf][2], s[2 * kf][3], pah[kf][1], pal[kf][1]);
            pack_split2(s[2 * kf + 1][0], s[2 * kf + 1][1], pah[kf][2], pal[kf][2]);
            pack_split2(s[2 * kf + 1][2], s[2 * kf + 1][3], pah[kf][3], pal[kf][3]);
        }

        // ---- O += P V (bf16x3) ----
        const int lrow16 = lane & 15;
#pragma unroll
        for (int n = 0; n < 16; n++) {
#pragma unroll
            for (int kf = 0; kf < 4; kf++) {
                int trow = kf * 16 + lrow16;
                u32 off = (u32)(trow * 256) + ((u32)(n ^ (trow & 7)) << 4);
                u32 bvh[2], bvl[2];
                ldsm_x2_t(bvh[0], bvh[1], sbase + VH_OFF + off);
                ldsm_x2_t(bvl[0], bvl[1], sbase + VL_OFF + off);
                mma16816(o[n], pah[kf], bvh);
                mma16816(o[n], pah[kf], bvl);
                mma16816(o[n], pal[kf], bvh);
            }
        }
    }

    // ---- normalize and store ----
    float inv0 = 1.f / l0, inv1 = 1.f / l1;
    {
        size_t r0 = (size_t)(b * TT + qt * 64 + warp * 16 + fr) * DD + h * HDIM;
        size_t r1 = r0 + (size_t)8 * DD;
#pragma unroll
        for (int n = 0; n < 16; n++) {
            int cc = n * 8 + 2 * fc;
            *(float2*)(y + r0 + cc) = make_float2(o[n][0] * inv0, o[n][1] * inv0);
            *(float2*)(y + r1 + cc) = make_float2(o[n][2] * inv1, o[n][3] * inv1);
        }
    }
}

// ---------------------------------------------------------------------------
// Launch
// ---------------------------------------------------------------------------
extern "C" void kernel_launch(void* const* d_in, const int* in_sizes, int n_in,
                              void* d_out, int out_size) {
    const float* x     = (const float*)d_in[0];
    const int*   mask  = (const int*)d_in[1];
    const float* w_qkv = (const float*)d_in[2];
    const float* w_o   = (const float*)d_in[3];
    float* out = (float*)d_out;

    float *qkv, *yb;
    cudaGetSymbolAddress((void**)&qkv, g_qkv);
    cudaGetSymbolAddress((void**)&yb, g_y);
    cudaFuncSetAttribute(attn_mma, cudaFuncAttributeMaxDynamicSharedMemorySize,
                         ATTN2_SMEM);

    // QKV = X @ Wqkv^T
    gemm_nt_tf32<<<dim3(3 * DD / BN, BB * TT / BM), 256>>>(x, w_qkv, qkv,
                                                           BB * TT, 3 * DD, DD);
    // Attention -> y (B,T,D)
    attn_mma<<<dim3(TT / 64, BB * HH), 128, ATTN2_SMEM>>>(qkv, mask, yb);
    // out = Y @ Wo^T
    gemm_nt_tf32<<<dim3(DD / BN, BB * TT / BM), 256>>>(yb, w_o, out,
                                                       BB * TT, DD, DD);
}